// round 1
// baseline (speedup 1.0000x reference)
#include <cuda_runtime.h>

#define NSEQ 1024
#define FEAT 768
#define ADIM 128
#define VOCAB 32000
#define NBLOCKS 96
#define KSPLIT 8

// ---------------- scratch (static device globals; no allocations) ----------
__device__ float g_h[NSEQ * FEAT];
__device__ float g_n1[NSEQ * FEAT];
__device__ float g_tmp[NSEQ * FEAT];
__device__ float g_q[NSEQ * ADIM];
__device__ float g_k[NSEQ * ADIM];
__device__ float g_v[NSEQ * ADIM];
__device__ float g_av[NSEQ * ADIM];
__device__ float g_s[NSEQ * NSEQ];
__device__ float g_part[KSPLIT][NSEQ * FEAT];
__device__ float g_logits[(size_t)NSEQ * VOCAB];

// ---------------- generic tiled SGEMM body ---------------------------------
// C[M,N] = A[M,K] * op(B) + bias[N] + add[M,N]
// TRANSB=false: B is [K,N] row-major.  TRANSB=true: B is [N,K] row-major.
template <int BM, int BN, int BK, int TM, int TN, bool TRANSB>
__device__ __forceinline__ void gemm_body(
    const float* __restrict__ A, const float* __restrict__ B,
    const float* __restrict__ bias, const float* __restrict__ add,
    float* __restrict__ C, int M, int N, int K, int kStart, int kLen)
{
    __shared__ float As[BK][BM];
    __shared__ float Bs[BK][BN];
    constexpr int THREADS = (BM / TM) * (BN / TN);
    const int tid = threadIdx.x;
    const int tx = tid % (BN / TN);
    const int ty = tid / (BN / TN);
    const int m0 = blockIdx.y * BM;
    const int n0 = blockIdx.x * BN;

    float acc[TM][TN];
#pragma unroll
    for (int i = 0; i < TM; i++)
#pragma unroll
        for (int j = 0; j < TN; j++) acc[i][j] = 0.f;

    for (int k0 = kStart; k0 < kStart + kLen; k0 += BK) {
        // load A tile (transpose into smem)
#pragma unroll 4
        for (int i = tid; i < BM * BK; i += THREADS) {
            int r = i / BK, c = i % BK;
            As[c][r] = A[(size_t)(m0 + r) * K + (k0 + c)];
        }
        // load B tile
        if (!TRANSB) {
#pragma unroll 4
            for (int i = tid; i < BK * BN; i += THREADS) {
                int r = i / BN, c = i % BN;
                Bs[r][c] = B[(size_t)(k0 + r) * N + (n0 + c)];
            }
        } else {
#pragma unroll 4
            for (int i = tid; i < BK * BN; i += THREADS) {
                int r = i / BK, c = i % BK;
                Bs[c][r] = B[(size_t)(n0 + r) * K + (k0 + c)];
            }
        }
        __syncthreads();

#pragma unroll
        for (int kk = 0; kk < BK; kk++) {
            float a[TM], b[TN];
#pragma unroll
            for (int i = 0; i < TM; i++) a[i] = As[kk][ty * TM + i];
#pragma unroll
            for (int j = 0; j < TN; j++) b[j] = Bs[kk][tx * TN + j];
#pragma unroll
            for (int i = 0; i < TM; i++)
#pragma unroll
                for (int j = 0; j < TN; j++) acc[i][j] += a[i] * b[j];
        }
        __syncthreads();
    }

#pragma unroll
    for (int i = 0; i < TM; i++) {
        int m = m0 + ty * TM + i;
#pragma unroll
        for (int j = 0; j < TN; j++) {
            int n = n0 + tx * TN + j;
            float v = acc[i][j];
            if (bias) v += bias[n];
            if (add) v += add[(size_t)m * N + n];
            C[(size_t)m * N + n] = v;
        }
    }
}

template <int BM, int BN, int BK, int TM, int TN, bool TRANSB>
__global__ void gemm_kernel(const float* __restrict__ A, const float* __restrict__ B,
                            const float* __restrict__ bias, const float* __restrict__ add,
                            float* __restrict__ C, int M, int N, int K)
{
    gemm_body<BM, BN, BK, TM, TN, TRANSB>(A, B, bias, add, C, M, N, K, 0, K);
}

// ---------------- embedding: split-K over VOCAB -----------------------------
__global__ void emb_splitk_kernel(const float* __restrict__ x, const float* __restrict__ W)
{
    const int s = blockIdx.z;
    constexpr int KC = VOCAB / KSPLIT;
    gemm_body<128, 128, 8, 8, 8, false>(x, W, nullptr, nullptr, g_part[s],
                                        NSEQ, FEAT, VOCAB, s * KC, KC);
}

__global__ void emb_reduce_kernel(const float* __restrict__ b_emb, const float* __restrict__ pe)
{
    int i = blockIdx.x * blockDim.x + threadIdx.x;
    if (i >= NSEQ * FEAT) return;
    float v = 0.f;
#pragma unroll
    for (int s = 0; s < KSPLIT; s++) v += g_part[s][i];
    g_h[i] = v + b_emb[i % FEAT] + pe[i];
}

// ---------------- fused Q/K/V projection (gridDim.z selects which) ---------
__global__ void qkv_kernel(const float* __restrict__ h,
                           const float* __restrict__ Wq, const float* __restrict__ bq,
                           const float* __restrict__ Wk, const float* __restrict__ bk,
                           const float* __restrict__ Wv, const float* __restrict__ bv)
{
    const float* W;
    const float* b;
    float* out;
    if (blockIdx.z == 0) { W = Wq; b = bq; out = g_q; }
    else if (blockIdx.z == 1) { W = Wk; b = bk; out = g_k; }
    else { W = Wv; b = bv; out = g_v; }
    gemm_body<64, 64, 8, 8, 4, false>(h, W, b, nullptr, out, NSEQ, ADIM, FEAT, 0, FEAT);
}

// ---------------- row softmax over g_s (1024 x 1024) ------------------------
__global__ void softmax_kernel()
{
    const int row = blockIdx.x;
    float4* S = reinterpret_cast<float4*>(g_s + (size_t)row * NSEQ);
    const int tid = threadIdx.x;  // 256 threads, 4 elems each
    float4 v = S[tid];
    __shared__ float red[8];

    float m = fmaxf(fmaxf(v.x, v.y), fmaxf(v.z, v.w));
#pragma unroll
    for (int o = 16; o > 0; o >>= 1) m = fmaxf(m, __shfl_xor_sync(0xffffffffu, m, o));
    if ((tid & 31) == 0) red[tid >> 5] = m;
    __syncthreads();
    if (tid == 0) {
        float mm = red[0];
#pragma unroll
        for (int i = 1; i < 8; i++) mm = fmaxf(mm, red[i]);
        red[0] = mm;
    }
    __syncthreads();
    m = red[0];
    __syncthreads();

    v.x = __expf(v.x - m); v.y = __expf(v.y - m);
    v.z = __expf(v.z - m); v.w = __expf(v.w - m);
    float s = v.x + v.y + v.z + v.w;
#pragma unroll
    for (int o = 16; o > 0; o >>= 1) s += __shfl_xor_sync(0xffffffffu, s, o);
    if ((tid & 31) == 0) red[tid >> 5] = s;
    __syncthreads();
    if (tid == 0) {
        float ss = 0.f;
#pragma unroll
        for (int i = 0; i < 8; i++) ss += red[i];
        red[0] = ss;
    }
    __syncthreads();
    float inv = 1.f / red[0];
    v.x *= inv; v.y *= inv; v.z *= inv; v.w *= inv;
    S[tid] = v;
}

// ---------------- row l2 normalize (rows of FEAT=768) -----------------------
__global__ void l2norm_kernel(const float* __restrict__ in, float* __restrict__ out)
{
    const int row = blockIdx.x;
    const float* r = in + (size_t)row * FEAT;
    const int tid = threadIdx.x;  // 256 threads
    float x0 = r[tid], x1 = r[tid + 256], x2 = r[tid + 512];
    float ss = x0 * x0 + x1 * x1 + x2 * x2;
    __shared__ float red[8];
#pragma unroll
    for (int o = 16; o > 0; o >>= 1) ss += __shfl_xor_sync(0xffffffffu, ss, o);
    if ((tid & 31) == 0) red[tid >> 5] = ss;
    __syncthreads();
    if (tid == 0) {
        float t = 0.f;
#pragma unroll
        for (int i = 0; i < 8; i++) t += red[i];
        red[0] = t;
    }
    __syncthreads();
    float sc = 1.f / fmaxf(sqrtf(red[0]), 1e-12f);
    float* o = out + (size_t)row * FEAT;
    o[tid] = x0 * sc; o[tid + 256] = x1 * sc; o[tid + 512] = x2 * sc;
}

// ---------------- top-k (k<=10) over sequence dim per vocab column ----------
__global__ void topk_kernel(const int* __restrict__ kptr, float* __restrict__ out)
{
    int v = blockIdx.x * blockDim.x + threadIdx.x;
    if (v >= VOCAB) return;
    float best[10];
#pragma unroll
    for (int i = 0; i < 10; i++) best[i] = -3.402823466e+38f;

    const float* L = g_logits + v;
#pragma unroll 4
    for (int n = 0; n < NSEQ; n++) {
        float x = L[(size_t)n * VOCAB];
        if (x > best[9]) {
            best[9] = x;
#pragma unroll
            for (int i = 9; i > 0; i--) {
                if (best[i] > best[i - 1]) {
                    float t = best[i - 1]; best[i - 1] = best[i]; best[i] = t;
                }
            }
        }
    }
    int k = *kptr;
    if (k > 10) k = 10;
    for (int i = 0; i < k; i++) out[(size_t)i * VOCAB + v] = best[i];
}

// ---------------- host orchestration ----------------------------------------
extern "C" void kernel_launch(void* const* d_in, const int* in_sizes, int n_in,
                              void* d_out, int out_size)
{
    const float* x    = (const float*)d_in[0];
    const float* pe   = (const float*)d_in[1];
    const float* Wemb = (const float*)d_in[2];
    const float* bemb = (const float*)d_in[3];
    const float* Wq   = (const float*)d_in[4];
    const float* bq   = (const float*)d_in[5];
    const float* Wk   = (const float*)d_in[6];
    const float* bk   = (const float*)d_in[7];
    const float* Wv   = (const float*)d_in[8];
    const float* bv   = (const float*)d_in[9];
    const float* Wo   = (const float*)d_in[10];
    const float* bo   = (const float*)d_in[11];
    const float* W1   = (const float*)d_in[12];
    const float* b1   = (const float*)d_in[13];
    const float* Wout = (const float*)d_in[14];
    const float* bout = (const float*)d_in[15];
    const int*   kptr = (const int*)d_in[16];
    float* out = (float*)d_out;

    float *h, *n1, *tmp, *q, *kx, *vx, *av, *s, *logits;
    cudaGetSymbolAddress((void**)&h, g_h);
    cudaGetSymbolAddress((void**)&n1, g_n1);
    cudaGetSymbolAddress((void**)&tmp, g_tmp);
    cudaGetSymbolAddress((void**)&q, g_q);
    cudaGetSymbolAddress((void**)&kx, g_k);
    cudaGetSymbolAddress((void**)&vx, g_v);
    cudaGetSymbolAddress((void**)&av, g_av);
    cudaGetSymbolAddress((void**)&s, g_s);
    cudaGetSymbolAddress((void**)&logits, g_logits);

    // --- embedding: h = x @ Wemb + bemb + pe (split-K over VOCAB) ---
    emb_splitk_kernel<<<dim3(FEAT / 128, NSEQ / 128, KSPLIT), 256>>>(x, Wemb);
    emb_reduce_kernel<<<(NSEQ * FEAT + 255) / 256, 256>>>(bemb, pe);

    // --- 96 transformer blocks ---
    for (int b = 0; b < NBLOCKS; b++) {
        // Q,K,V = h @ W{q,k,v} + b
        qkv_kernel<<<dim3(ADIM / 64, NSEQ / 64, 3), 128>>>(h, Wq, bq, Wk, bk, Wv, bv);
        // S = Q @ K^T
        gemm_kernel<64, 64, 8, 8, 4, true><<<dim3(NSEQ / 64, NSEQ / 64), 128>>>(
            q, kx, nullptr, nullptr, s, NSEQ, NSEQ, ADIM);
        softmax_kernel<<<NSEQ, 256>>>();
        // AV = softmax(S) @ V
        gemm_kernel<64, 64, 8, 8, 4, false><<<dim3(ADIM / 64, NSEQ / 64), 128>>>(
            s, vx, nullptr, nullptr, av, NSEQ, ADIM, NSEQ);
        // tmp = h + AV @ Wo + bo
        gemm_kernel<64, 64, 8, 8, 4, false><<<dim3(FEAT / 64, NSEQ / 64), 128>>>(
            av, Wo, bo, h, tmp, NSEQ, FEAT, ADIM);
        // n1 = l2norm(tmp)
        l2norm_kernel<<<NSEQ, 256>>>(tmp, n1);
        // tmp = n1 + n1 @ W1 + b1   (r2)
        gemm_kernel<64, 64, 8, 8, 4, false><<<dim3(FEAT / 64, NSEQ / 64), 128>>>(
            n1, W1, b1, n1, tmp, NSEQ, FEAT, FEAT);
        // n1 = r2 @ W1 + b1
        gemm_kernel<64, 64, 8, 8, 4, false><<<dim3(FEAT / 64, NSEQ / 64), 128>>>(
            tmp, W1, b1, nullptr, n1, NSEQ, FEAT, FEAT);
        // h = l2norm(n1)
        l2norm_kernel<<<NSEQ, 256>>>(n1, h);
    }

    // --- logits = h @ Wout + bout ---
    gemm_kernel<128, 128, 8, 8, 8, false><<<dim3(VOCAB / 128, NSEQ / 128), 256>>>(
        h, Wout, bout, nullptr, logits, NSEQ, VOCAB, FEAT);

    // --- top-k over sequence dim ---
    topk_kernel<<<(VOCAB + 127) / 128, 128>>>(kptr, out);
}

// round 2
// speedup vs baseline: 2.3556x; 2.3556x over previous
#include <cuda_runtime.h>

#define NSEQ 1024
#define FEAT 768
#define ADIM 128
#define VOCAB 32000
#define NBLOCKS 96
#define KSPLIT 8

// ---------------- scratch (static device globals; no allocations) ----------
__device__ float g_h[NSEQ * FEAT];
__device__ float g_n1[NSEQ * FEAT];
__device__ float g_tmp[NSEQ * FEAT];
__device__ float g_q[NSEQ * ADIM];
__device__ float g_k[NSEQ * ADIM];
__device__ float g_v[NSEQ * ADIM];
__device__ float g_av[NSEQ * ADIM];
__device__ float g_s[NSEQ * NSEQ];
__device__ float g_part[KSPLIT][NSEQ * FEAT];
__device__ float g_logits[(size_t)NSEQ * VOCAB];

// ---------------- vectorized double-buffered SGEMM --------------------------
// C[M,N] = A[M,K] * op(B) + bias[N] + add[M,N]
// TRANSB=false: B is [K,N] row-major.  TRANSB=true: B is [N,K] row-major.
// Requires: M%BM==0, N%BN==0, kLen%BK==0, K%4==0.
template <int BM, int BN, int BK, int TM, int TN, bool TRANSB>
__device__ __forceinline__ void gemm_body(
    const float* __restrict__ A, const float* __restrict__ B,
    const float* __restrict__ bias, const float* __restrict__ add,
    float* __restrict__ C, int M, int N, int K, int kStart, int kLen)
{
    constexpr int THREADS = (BM / TM) * (BN / TN);
    constexpr int PAD = 4;
    __shared__ __align__(16) float As[2][BK][BM + PAD];
    __shared__ __align__(16) float Bs[2][BK][BN + PAD];
    constexpr int NA = (BM * BK) / (4 * THREADS);
    constexpr int NB = (BK * BN) / (4 * THREADS);
    static_assert(NA >= 1 && NB >= 1, "tile too small");

    const int tid = threadIdx.x;
    const int tx = tid % (BN / TN);
    const int ty = tid / (BN / TN);
    const int m0 = blockIdx.y * BM;
    const int n0 = blockIdx.x * BN;

    float acc[TM][TN];
#pragma unroll
    for (int i = 0; i < TM; i++)
#pragma unroll
        for (int j = 0; j < TN; j++) acc[i][j] = 0.f;

    float4 ar[NA], br[NB];

    auto loadA = [&](int k0) {
#pragma unroll
        for (int i = 0; i < NA; i++) {
            int f = tid + i * THREADS;
            int row = f / (BK / 4);
            int kq = f % (BK / 4);
            ar[i] = *reinterpret_cast<const float4*>(
                &A[(size_t)(m0 + row) * K + k0 + kq * 4]);
        }
    };
    auto storeA = [&](int buf) {
#pragma unroll
        for (int i = 0; i < NA; i++) {
            int f = tid + i * THREADS;
            int row = f / (BK / 4);
            int kq = f % (BK / 4);
            As[buf][kq * 4 + 0][row] = ar[i].x;
            As[buf][kq * 4 + 1][row] = ar[i].y;
            As[buf][kq * 4 + 2][row] = ar[i].z;
            As[buf][kq * 4 + 3][row] = ar[i].w;
        }
    };
    auto loadB = [&](int k0) {
        if (!TRANSB) {
#pragma unroll
            for (int i = 0; i < NB; i++) {
                int f = tid + i * THREADS;
                int row = f / (BN / 4);
                int cq = f % (BN / 4);
                br[i] = *reinterpret_cast<const float4*>(
                    &B[(size_t)(k0 + row) * N + n0 + cq * 4]);
            }
        } else {
#pragma unroll
            for (int i = 0; i < NB; i++) {
                int f = tid + i * THREADS;
                int row = f / (BK / 4);  // n index within tile
                int kq = f % (BK / 4);
                br[i] = *reinterpret_cast<const float4*>(
                    &B[(size_t)(n0 + row) * K + k0 + kq * 4]);
            }
        }
    };
    auto storeB = [&](int buf) {
        if (!TRANSB) {
#pragma unroll
            for (int i = 0; i < NB; i++) {
                int f = tid + i * THREADS;
                int row = f / (BN / 4);
                int cq = f % (BN / 4);
                *reinterpret_cast<float4*>(&Bs[buf][row][cq * 4]) = br[i];
            }
        } else {
#pragma unroll
            for (int i = 0; i < NB; i++) {
                int f = tid + i * THREADS;
                int row = f / (BK / 4);
                int kq = f % (BK / 4);
                Bs[buf][kq * 4 + 0][row] = br[i].x;
                Bs[buf][kq * 4 + 1][row] = br[i].y;
                Bs[buf][kq * 4 + 2][row] = br[i].z;
                Bs[buf][kq * 4 + 3][row] = br[i].w;
            }
        }
    };
    auto compute = [&](int buf) {
#pragma unroll
        for (int kk = 0; kk < BK; kk++) {
            float a[TM], b[TN];
#pragma unroll
            for (int i = 0; i < TM; i += 4) {
                float4 t = *reinterpret_cast<const float4*>(&As[buf][kk][ty * TM + i]);
                a[i] = t.x; a[i + 1] = t.y; a[i + 2] = t.z; a[i + 3] = t.w;
            }
#pragma unroll
            for (int j = 0; j < TN; j += 4) {
                float4 t = *reinterpret_cast<const float4*>(&Bs[buf][kk][tx * TN + j]);
                b[j] = t.x; b[j + 1] = t.y; b[j + 2] = t.z; b[j + 3] = t.w;
            }
#pragma unroll
            for (int i = 0; i < TM; i++)
#pragma unroll
                for (int j = 0; j < TN; j++) acc[i][j] += a[i] * b[j];
        }
    };

    // prologue
    loadA(kStart); loadB(kStart);
    storeA(0); storeB(0);
    __syncthreads();

    int buf = 0;
    for (int k0 = kStart + BK; k0 < kStart + kLen; k0 += BK) {
        loadA(k0); loadB(k0);       // global -> regs (overlaps compute)
        compute(buf);
        storeA(buf ^ 1); storeB(buf ^ 1);
        __syncthreads();
        buf ^= 1;
    }
    compute(buf);

    // epilogue (float4 stores)
#pragma unroll
    for (int i = 0; i < TM; i++) {
        int m = m0 + ty * TM + i;
#pragma unroll
        for (int j = 0; j < TN; j += 4) {
            int n = n0 + tx * TN + j;
            float4 v;
            v.x = acc[i][j]; v.y = acc[i][j + 1];
            v.z = acc[i][j + 2]; v.w = acc[i][j + 3];
            if (bias) {
                float4 bb = *reinterpret_cast<const float4*>(&bias[n]);
                v.x += bb.x; v.y += bb.y; v.z += bb.z; v.w += bb.w;
            }
            if (add) {
                float4 aa = *reinterpret_cast<const float4*>(&add[(size_t)m * N + n]);
                v.x += aa.x; v.y += aa.y; v.z += aa.z; v.w += aa.w;
            }
            *reinterpret_cast<float4*>(&C[(size_t)m * N + n]) = v;
        }
    }
}

template <int BM, int BN, int BK, int TM, int TN, bool TRANSB>
__global__ void gemm_kernel(const float* __restrict__ A, const float* __restrict__ B,
                            const float* __restrict__ bias, const float* __restrict__ add,
                            float* __restrict__ C, int M, int N, int K)
{
    gemm_body<BM, BN, BK, TM, TN, TRANSB>(A, B, bias, add, C, M, N, K, 0, K);
}

// ---------------- embedding: split-K over VOCAB -----------------------------
__global__ void emb_splitk_kernel(const float* __restrict__ x, const float* __restrict__ W)
{
    const int s = blockIdx.z;
    constexpr int KC = VOCAB / KSPLIT;
    gemm_body<128, 64, 16, 8, 4, false>(x, W, nullptr, nullptr, g_part[s],
                                        NSEQ, FEAT, VOCAB, s * KC, KC);
}

__global__ void emb_reduce_kernel(const float* __restrict__ b_emb, const float* __restrict__ pe)
{
    int i4 = blockIdx.x * blockDim.x + threadIdx.x;  // over NSEQ*FEAT/4
    if (i4 >= NSEQ * FEAT / 4) return;
    float4 v = make_float4(0.f, 0.f, 0.f, 0.f);
#pragma unroll
    for (int s = 0; s < KSPLIT; s++) {
        float4 p = reinterpret_cast<const float4*>(g_part[s])[i4];
        v.x += p.x; v.y += p.y; v.z += p.z; v.w += p.w;
    }
    int col = (i4 * 4) % FEAT;
    float4 bb = *reinterpret_cast<const float4*>(&b_emb[col]);
    float4 pp = reinterpret_cast<const float4*>(pe)[i4];
    v.x += bb.x + pp.x; v.y += bb.y + pp.y; v.z += bb.z + pp.z; v.w += bb.w + pp.w;
    reinterpret_cast<float4*>(g_h)[i4] = v;
}

// ---------------- fused Q/K/V projection (gridDim.z selects which) ---------
__global__ void qkv_kernel(const float* __restrict__ h,
                           const float* __restrict__ Wq, const float* __restrict__ bq,
                           const float* __restrict__ Wk, const float* __restrict__ bk,
                           const float* __restrict__ Wv, const float* __restrict__ bv)
{
    const float* W;
    const float* b;
    float* out;
    if (blockIdx.z == 0) { W = Wq; b = bq; out = g_q; }
    else if (blockIdx.z == 1) { W = Wk; b = bk; out = g_k; }
    else { W = Wv; b = bv; out = g_v; }
    gemm_body<64, 64, 16, 4, 4, false>(h, W, b, nullptr, out, NSEQ, ADIM, FEAT, 0, FEAT);
}

// ---------------- row softmax over g_s (1024 x 1024) ------------------------
__global__ void softmax_kernel()
{
    const int row = blockIdx.x;
    float4* S = reinterpret_cast<float4*>(g_s + (size_t)row * NSEQ);
    const int tid = threadIdx.x;  // 256 threads, 4 elems each
    float4 v = S[tid];
    __shared__ float red[8];

    float m = fmaxf(fmaxf(v.x, v.y), fmaxf(v.z, v.w));
#pragma unroll
    for (int o = 16; o > 0; o >>= 1) m = fmaxf(m, __shfl_xor_sync(0xffffffffu, m, o));
    if ((tid & 31) == 0) red[tid >> 5] = m;
    __syncthreads();
    if (tid == 0) {
        float mm = red[0];
#pragma unroll
        for (int i = 1; i < 8; i++) mm = fmaxf(mm, red[i]);
        red[0] = mm;
    }
    __syncthreads();
    m = red[0];
    __syncthreads();

    v.x = __expf(v.x - m); v.y = __expf(v.y - m);
    v.z = __expf(v.z - m); v.w = __expf(v.w - m);
    float s = v.x + v.y + v.z + v.w;
#pragma unroll
    for (int o = 16; o > 0; o >>= 1) s += __shfl_xor_sync(0xffffffffu, s, o);
    if ((tid & 31) == 0) red[tid >> 5] = s;
    __syncthreads();
    if (tid == 0) {
        float ss = 0.f;
#pragma unroll
        for (int i = 0; i < 8; i++) ss += red[i];
        red[0] = ss;
    }
    __syncthreads();
    float inv = 1.f / red[0];
    v.x *= inv; v.y *= inv; v.z *= inv; v.w *= inv;
    S[tid] = v;
}

// ---------------- row l2 normalize (rows of FEAT=768) -----------------------
__global__ void l2norm_kernel(const float* __restrict__ in, float* __restrict__ out)
{
    const int row = blockIdx.x;
    const float* r = in + (size_t)row * FEAT;
    const int tid = threadIdx.x;  // 256 threads
    float x0 = r[tid], x1 = r[tid + 256], x2 = r[tid + 512];
    float ss = x0 * x0 + x1 * x1 + x2 * x2;
    __shared__ float red[8];
#pragma unroll
    for (int o = 16; o > 0; o >>= 1) ss += __shfl_xor_sync(0xffffffffu, ss, o);
    if ((tid & 31) == 0) red[tid >> 5] = ss;
    __syncthreads();
    if (tid == 0) {
        float t = 0.f;
#pragma unroll
        for (int i = 0; i < 8; i++) t += red[i];
        red[0] = t;
    }
    __syncthreads();
    float sc = 1.f / fmaxf(sqrtf(red[0]), 1e-12f);
    float* o = out + (size_t)row * FEAT;
    o[tid] = x0 * sc; o[tid + 256] = x1 * sc; o[tid + 512] = x2 * sc;
}

// ---------------- top-k (k<=10) over sequence dim per vocab column ----------
__global__ void topk_kernel(const int* __restrict__ kptr, float* __restrict__ out)
{
    int v = blockIdx.x * blockDim.x + threadIdx.x;
    if (v >= VOCAB) return;
    float best[10];
#pragma unroll
    for (int i = 0; i < 10; i++) best[i] = -3.402823466e+38f;

    const float* L = g_logits + v;
#pragma unroll 4
    for (int n = 0; n < NSEQ; n++) {
        float x = L[(size_t)n * VOCAB];
        if (x > best[9]) {
            best[9] = x;
#pragma unroll
            for (int i = 9; i > 0; i--) {
                if (best[i] > best[i - 1]) {
                    float t = best[i - 1]; best[i - 1] = best[i]; best[i] = t;
                }
            }
        }
    }
    int k = *kptr;
    if (k > 10) k = 10;
    for (int i = 0; i < k; i++) out[(size_t)i * VOCAB + v] = best[i];
}

// ---------------- host orchestration ----------------------------------------
extern "C" void kernel_launch(void* const* d_in, const int* in_sizes, int n_in,
                              void* d_out, int out_size)
{
    const float* x    = (const float*)d_in[0];
    const float* pe   = (const float*)d_in[1];
    const float* Wemb = (const float*)d_in[2];
    const float* bemb = (const float*)d_in[3];
    const float* Wq   = (const float*)d_in[4];
    const float* bq   = (const float*)d_in[5];
    const float* Wk   = (const float*)d_in[6];
    const float* bk   = (const float*)d_in[7];
    const float* Wv   = (const float*)d_in[8];
    const float* bv   = (const float*)d_in[9];
    const float* Wo   = (const float*)d_in[10];
    const float* bo   = (const float*)d_in[11];
    const float* W1   = (const float*)d_in[12];
    const float* b1   = (const float*)d_in[13];
    const float* Wout = (const float*)d_in[14];
    const float* bout = (const float*)d_in[15];
    const int*   kptr = (const int*)d_in[16];
    float* out = (float*)d_out;

    float *h, *n1, *tmp, *q, *kx, *vx, *av, *s, *logits;
    cudaGetSymbolAddress((void**)&h, g_h);
    cudaGetSymbolAddress((void**)&n1, g_n1);
    cudaGetSymbolAddress((void**)&tmp, g_tmp);
    cudaGetSymbolAddress((void**)&q, g_q);
    cudaGetSymbolAddress((void**)&kx, g_k);
    cudaGetSymbolAddress((void**)&vx, g_v);
    cudaGetSymbolAddress((void**)&av, g_av);
    cudaGetSymbolAddress((void**)&s, g_s);
    cudaGetSymbolAddress((void**)&logits, g_logits);

    // --- embedding: h = x @ Wemb + bemb + pe (split-K over VOCAB) ---
    emb_splitk_kernel<<<dim3(FEAT / 64, NSEQ / 128, KSPLIT), 256>>>(x, Wemb);
    emb_reduce_kernel<<<(NSEQ * FEAT / 4 + 255) / 256, 256>>>(bemb, pe);

    // --- 96 transformer blocks ---
    for (int b = 0; b < NBLOCKS; b++) {
        // Q,K,V = h @ W{q,k,v} + b
        qkv_kernel<<<dim3(ADIM / 64, NSEQ / 64, 3), 256>>>(h, Wq, bq, Wk, bk, Wv, bv);
        // S = Q @ K^T
        gemm_kernel<64, 64, 16, 4, 4, true><<<dim3(NSEQ / 64, NSEQ / 64), 256>>>(
            q, kx, nullptr, nullptr, s, NSEQ, NSEQ, ADIM);
        softmax_kernel<<<NSEQ, 256>>>();
        // AV = softmax(S) @ V   (thin N -> 32-row tiles for more blocks)
        gemm_kernel<32, 64, 16, 4, 4, false><<<dim3(ADIM / 64, NSEQ / 32), 128>>>(
            s, vx, nullptr, nullptr, av, NSEQ, ADIM, NSEQ);
        // tmp = h + AV @ Wo + bo
        gemm_kernel<64, 64, 16, 4, 4, false><<<dim3(FEAT / 64, NSEQ / 64), 256>>>(
            av, Wo, bo, h, tmp, NSEQ, FEAT, ADIM);
        // n1 = l2norm(tmp)
        l2norm_kernel<<<NSEQ, 256>>>(tmp, n1);
        // tmp = n1 + n1 @ W1 + b1   (r2)
        gemm_kernel<64, 64, 16, 4, 4, false><<<dim3(FEAT / 64, NSEQ / 64), 256>>>(
            n1, W1, b1, n1, tmp, NSEQ, FEAT, FEAT);
        // n1 = r2 @ W1 + b1
        gemm_kernel<64, 64, 16, 4, 4, false><<<dim3(FEAT / 64, NSEQ / 64), 256>>>(
            tmp, W1, b1, nullptr, n1, NSEQ, FEAT, FEAT);
        // h = l2norm(n1)
        l2norm_kernel<<<NSEQ, 256>>>(n1, h);
    }

    // --- logits = h @ Wout + bout ---
    gemm_kernel<128, 64, 16, 8, 4, false><<<dim3(VOCAB / 64, NSEQ / 128), 256>>>(
        h, Wout, bout, nullptr, logits, NSEQ, VOCAB, FEAT);

    // --- top-k over sequence dim ---
    topk_kernel<<<(VOCAB + 127) / 128, 128>>>(kptr, out);
}